// round 8
// baseline (speedup 1.0000x reference)
#include <cuda_runtime.h>

// Causal FIR: y[row][t] = sum_{k=0}^{15} b[k] * x[row][t-k], zero init.
// x: [64, 480000] f32, b: [16] f32, y: [64, 480000] f32.
// R7: OUTS=8 mapping made every LDG.128 sector-sparse (32B lane stride ->
// 8 wavefronts/instr at 50% sector utilization). OUTS=4 restores fully
// coalesced 16B lane stride (4 wf/instr): 0.1875 wf/output vs 0.25.
// Taps stay in __constant__ (R6 win). Expect DRAM to become the binder.

#define N_TAPS 16
#define T_LEN 480000
#define BATCH 64
#define OUTS_PER_THREAD 4

__constant__ float c_taps[N_TAPS];

__global__ __launch_bounds__(256) void fir_kernel(
    const float* __restrict__ x,
    float* __restrict__ y)
{
    const int row = blockIdx.y;
    const int t0  = (blockIdx.x * blockDim.x + threadIdx.x) * OUTS_PER_THREAD;
    if (t0 >= T_LEN) return;

    const float* __restrict__ xr = x + (size_t)row * T_LEN;

    // v[i] = x[t0 - 16 + i], i in [0, 20). t0 % 4 == 0 -> 16B-aligned base:
    // 5 aligned float4 loads, fully coalesced across the warp (lane stride
    // 16B), front-batched (MLP=5). Halo repeats hit L1.
    float v[20];
    if (t0 >= N_TAPS) {
        const float4* __restrict__ p =
            reinterpret_cast<const float4*>(xr + t0 - 16);
        #pragma unroll
        for (int i = 0; i < 5; i++) {
            float4 f = p[i];
            v[4*i + 0] = f.x;
            v[4*i + 1] = f.y;
            v[4*i + 2] = f.z;
            v[4*i + 3] = f.w;
        }
    } else {
        // Row head: zero-padded shift register. 4 threads/row.
        #pragma unroll
        for (int i = 0; i < 20; i++) {
            int idx = t0 - 16 + i;
            v[i] = (idx >= 0) ? xr[idx] : 0.0f;
        }
    }

    // y[t0+j] = sum_k c_taps[k] * v[16 + j - k]; taps via constant port.
    float acc[OUTS_PER_THREAD];
    #pragma unroll
    for (int j = 0; j < OUTS_PER_THREAD; j++) {
        float a = 0.0f;
        #pragma unroll
        for (int k = 0; k < N_TAPS; k++) {
            a = fmaf(c_taps[k], v[16 + j - k], a);
        }
        acc[j] = a;
    }

    float4 o;
    o.x = acc[0]; o.y = acc[1]; o.z = acc[2]; o.w = acc[3];
    *reinterpret_cast<float4*>(y + (size_t)row * T_LEN + t0) = o;
}

extern "C" void kernel_launch(void* const* d_in, const int* in_sizes, int n_in,
                              void* d_out, int out_size)
{
    const float* x = (const float*)d_in[0];
    const float* b = (const float*)d_in[1];
    float* y = (float*)d_out;

    // Taps -> constant bank (64 B D2D async copy; graph-capturable).
    cudaMemcpyToSymbolAsync(c_taps, b, N_TAPS * sizeof(float), 0,
                            cudaMemcpyDeviceToDevice, 0);

    const int threads = 256;
    const int threads_per_row = T_LEN / OUTS_PER_THREAD;          // 120000
    dim3 grid((threads_per_row + threads - 1) / threads, BATCH);  // (469, 64)
    fir_kernel<<<grid, threads>>>(x, y);
}